// round 2
// baseline (speedup 1.0000x reference)
#include <cuda_runtime.h>
#include <cstddef>

#define NBOX 1024
#define S    32
#define C    64
#define HF   192
#define WF   192
#define IST  244   // per-ic stride in sIn (6 rows * 40 slots + 4 pad; %4==0 for float4, gcd(20,32)=4 -> only 4-way STS conflict on fill)

// Ping-pong scratch (no allocation allowed -> __device__ globals)
__device__ float g_buf0[NBOX * S * S * C];
__device__ float g_buf1[NBOX * S * S * C];

// ---------------- packed fp32x2 helpers (sm_100+ PTX) ----------------
__device__ __forceinline__ unsigned long long bcast2(float x) {
    unsigned long long r;
    unsigned u = __float_as_uint(x);
    asm("mov.b64 %0, {%1, %1};" : "=l"(r) : "r"(u));
    return r;
}
__device__ __forceinline__ void ffma2(unsigned long long& acc,
                                      unsigned long long a,
                                      unsigned long long b) {
    asm("fma.rn.f32x2 %0, %1, %2, %0;" : "+l"(acc) : "l"(a), "l"(b));
}
union U64F2 { unsigned long long u; float2 f; };

// ---------------- Kernel 1: crop_and_resize ----------------
// One block per (box, output row). 256 threads: x = tid>>3 (32), c0 = (tid&7)*8.
__global__ void __launch_bounds__(256) crop_kernel(const float* __restrict__ feat,
                                                   const float* __restrict__ boxes,
                                                   const int* __restrict__ box_ids) {
    int blk = blockIdx.x;
    int box = blk >> 5;
    int y   = blk & 31;
    int tid = threadIdx.x;

    float by1 = boxes[box * 4 + 0];
    float bx1 = boxes[box * 4 + 1];
    float by2 = boxes[box * 4 + 2];
    float bx2 = boxes[box * 4 + 3];
    int   bi  = box_ids[box];

    float ty = (float)y * (1.0f / 31.0f);
    float ys = (by1 + ty * (by2 - by1)) * 191.0f;
    float y0f = fminf(fmaxf(floorf(ys), 0.0f), 191.0f);
    float wy = ys - y0f;
    int y0i = (int)y0f;
    int y1i = min(y0i + 1, 191);

    int x  = tid >> 3;
    int c0 = (tid & 7) * 8;
    float tx = (float)x * (1.0f / 31.0f);
    float xs = (bx1 + tx * (bx2 - bx1)) * 191.0f;
    float x0f = fminf(fmaxf(floorf(xs), 0.0f), 191.0f);
    float wx = xs - x0f;
    int x0i = (int)x0f;
    int x1i = min(x0i + 1, 191);

    const float* fb = feat + (size_t)bi * HF * WF * C;
    const float4* p00 = (const float4*)(fb + ((size_t)y0i * WF + x0i) * C + c0);
    const float4* p01 = (const float4*)(fb + ((size_t)y0i * WF + x1i) * C + c0);
    const float4* p10 = (const float4*)(fb + ((size_t)y1i * WF + x0i) * C + c0);
    const float4* p11 = (const float4*)(fb + ((size_t)y1i * WF + x1i) * C + c0);

    float omwx = 1.0f - wx, omwy = 1.0f - wy;
    float4* o = (float4*)(g_buf0 + ((size_t)(box * S + y) * S + x) * C + c0);

#pragma unroll
    for (int h = 0; h < 2; h++) {
        float4 v00 = p00[h], v01 = p01[h], v10 = p10[h], v11 = p11[h];
        float4 r;
        r.x = (v00.x * omwx + v01.x * wx) * omwy + (v10.x * omwx + v11.x * wx) * wy;
        r.y = (v00.y * omwx + v01.y * wx) * omwy + (v10.y * omwx + v11.y * wx) * wy;
        r.z = (v00.z * omwx + v01.z * wx) * omwy + (v10.z * omwx + v11.z * wx) * wy;
        r.w = (v00.w * omwx + v01.w * wx) * omwy + (v10.w * omwx + v11.w * wx) * wy;
        o[h] = r;
    }
}

// ---------------- Kernel 2: 3x3 SAME conv 64->64 + ReLU ----------------
// Block = (rowtile of 4 rows [blockIdx.x], box [blockIdx.y]). 256 threads.
// Thread: ocg = tid&15 -> oc0=4*ocg ; pg = tid>>4 -> j = pg>>2 (row), x0 = (pg&3)*8.
// smem: sIn[64][IST] transposed (ic-major, rows y0-1..y0+4, x slots 0..39 with x+4 shift,
//       pads zero for SAME padding) + sW[3][64][64] = one ky weight slice.
__global__ void __launch_bounds__(256, 2) conv3_relu_kernel(const float* __restrict__ w,
                                                            const float* __restrict__ bias,
                                                            int dir) {
    extern __shared__ float sm[];
    float* sIn = sm;                 // 64 * IST floats
    float* sW  = sm + 64 * IST;      // 3*64*64 floats

    const float* in  = dir ? g_buf1 : g_buf0;
    float*       out = dir ? g_buf0 : g_buf1;

    int box = blockIdx.y;
    int y0  = blockIdx.x * 4;
    int tid = threadIdx.x;

    // zero the whole transposed tile (covers SAME padding + x-slot pads)
    for (int e = tid; e < 64 * IST; e += 256) sIn[e] = 0.0f;
    __syncthreads();

    // fill valid region: read [gy][x][c] coalesced over c, store transposed
    const float* inb = in + (size_t)box * S * S * C;
    for (int e = tid; e < 64 * 6 * 32; e += 256) {
        int c  = e & 63;
        int xx = (e >> 6) & 31;
        int r  = e >> 11;
        int gy = y0 - 1 + r;
        if ((unsigned)gy < 32u)
            sIn[c * IST + r * 40 + 4 + xx] = inb[((size_t)(gy * 32 + xx)) * C + c];
    }

    int ocg = tid & 15, pg = tid >> 4;
    int oc0 = ocg * 4;
    int j   = pg >> 2;        // output row within tile
    int x0  = (pg & 3) * 8;   // first of 8 consecutive x

    unsigned long long acc[8][2];
#pragma unroll
    for (int p = 0; p < 8; p++) { acc[p][0] = 0ull; acc[p][1] = 0ull; }

    for (int ky = 0; ky < 3; ky++) {
        __syncthreads();
        // stage weight slice for this ky (contiguous 12288 floats)
        for (int e = tid; e < 3 * 64 * 64; e += 256) sW[e] = w[ky * (3 * 64 * 64) + e];
        __syncthreads();

        const float* rowp = sIn + (j + ky) * 40 + x0;  // slot x0 == input x (x0-4)
#pragma unroll 2
        for (int ic = 0; ic < 64; ic++) {
            const float4* a4 = (const float4*)(rowp + ic * IST);
            float4 A0 = a4[0], A1 = a4[1], A2 = a4[2], A3 = a4[3];
            // window covers input x in [x0-4, x0+12); needed: x0-1..x0+8 -> idx 3..12
            unsigned long long pv[10];
            pv[0] = bcast2(A0.w);
            pv[1] = bcast2(A1.x); pv[2] = bcast2(A1.y); pv[3] = bcast2(A1.z); pv[4] = bcast2(A1.w);
            pv[5] = bcast2(A2.x); pv[6] = bcast2(A2.y); pv[7] = bcast2(A2.z); pv[8] = bcast2(A2.w);
            pv[9] = bcast2(A3.x);
#pragma unroll
            for (int kx = 0; kx < 3; kx++) {
                ulonglong2 wk = *(const ulonglong2*)(sW + (kx * 64 + ic) * 64 + oc0);
#pragma unroll
                for (int p = 0; p < 8; p++) {
                    ffma2(acc[p][0], pv[p + kx], wk.x);
                    ffma2(acc[p][1], pv[p + kx], wk.y);
                }
            }
        }
    }

    float b0 = bias[oc0], b1 = bias[oc0 + 1], b2 = bias[oc0 + 2], b3 = bias[oc0 + 3];
    float* ob = out + (((size_t)box * S + (y0 + j)) * S + x0) * C + oc0;
#pragma unroll
    for (int p = 0; p < 8; p++) {
        U64F2 lo, hi;
        lo.u = acc[p][0];
        hi.u = acc[p][1];
        float4 v;
        v.x = fmaxf(lo.f.x + b0, 0.0f);
        v.y = fmaxf(lo.f.y + b1, 0.0f);
        v.z = fmaxf(hi.f.x + b2, 0.0f);
        v.w = fmaxf(hi.f.y + b3, 0.0f);
        *(float4*)(ob + (size_t)p * C) = v;
    }
}

// ---------------- Kernel 3: 3x3 VALID conv 64->3, only the selected class ----------------
__global__ void __launch_bounds__(256) outconv_kernel(const float* __restrict__ ow,
                                                      const float* __restrict__ obias,
                                                      const int* __restrict__ cls,
                                                      float* __restrict__ out) {
    __shared__ float sW[576];
    int box = blockIdx.x;
    int cl  = cls[box];
    int tid = threadIdx.x;
    for (int e = tid; e < 576; e += 256) sW[e] = ow[e * 3 + cl];
    __syncthreads();
    float bb = obias[cl];
    const float* inb = g_buf0 + (size_t)box * S * S * C;

    for (int p = tid; p < 900; p += 256) {
        int oy = p / 30;
        int ox = p - oy * 30;
        float acc = 0.0f;
        for (int ky = 0; ky < 3; ky++) {
            for (int kx = 0; kx < 3; kx++) {
                const float4* iv = (const float4*)(inb + ((size_t)((oy + ky) * 32 + (ox + kx))) * C);
                const float4* wv = (const float4*)(sW + (ky * 3 + kx) * 64);
#pragma unroll
                for (int q = 0; q < 16; q++) {
                    float4 a = iv[q], b = wv[q];
                    acc += a.x * b.x + a.y * b.y + a.z * b.z + a.w * b.w;
                }
            }
        }
        out[(size_t)box * 900 + p] = acc + bb;
    }
}

// ---------------- launch ----------------
extern "C" void kernel_launch(void* const* d_in, const int* in_sizes, int n_in,
                              void* d_out, int out_size) {
    const float* features = (const float*)d_in[0];
    const float* boxes    = (const float*)d_in[1];
    const int*   box_ids  = (const int*)d_in[2];
    const int*   cls      = (const int*)d_in[3];
    const float* c1w      = (const float*)d_in[4];
    const float* c1b      = (const float*)d_in[5];
    const float* c2w      = (const float*)d_in[6];
    const float* c2b      = (const float*)d_in[7];
    const float* ow       = (const float*)d_in[8];
    const float* obias    = (const float*)d_in[9];
    float* out = (float*)d_out;

    const int conv_smem = (64 * IST + 3 * 64 * 64) * (int)sizeof(float);  // 111616 B
    cudaFuncSetAttribute(conv3_relu_kernel,
                         cudaFuncAttributeMaxDynamicSharedMemorySize, conv_smem);

    crop_kernel<<<NBOX * S, 256>>>(features, boxes, box_ids);
    conv3_relu_kernel<<<dim3(8, NBOX), 256, conv_smem>>>(c1w, c1b, 0);  // buf0 -> buf1
    conv3_relu_kernel<<<dim3(8, NBOX), 256, conv_smem>>>(c2w, c2b, 1);  // buf1 -> buf0
    outconv_kernel<<<NBOX, 256>>>(ow, obias, cls, out);
}